// round 10
// baseline (speedup 1.0000x reference)
#include <cuda_runtime.h>
#include <cuda_fp16.h>

#define NN 200000
#define NE 400000
#define NG 64
#define HD 128
#define IND 5
#define TROWS 64
#define SROW 136        // f16 tile row stride (halves): ldmatrix conflict-free
#define SPST 12         // partial-sum row stride (floats): 48B, 16B-aligned
#define GRID_P 304      // persistent CTAs (2 per SM)
#define NSB 196         // scan blocks: ceil(NN/1024)

// ---------------- device scratch (allocation-free rule) ----------------
__device__ float  g_h5[NN * IND];
__device__ __half g_h[(size_t)NN * HD];     // accumulation result (y + aggr), fp16
__device__ __half g_bufA[(size_t)NN * HD];
__device__ __half g_bufB[(size_t)NN * HD];
__device__ float  g_pool[NG * HD];
__device__ int    g_cnt[NG];
// CSR by destination (built once, reused by all 3 layers)
__device__ int g_deg[NN];
__device__ int g_off[NN];
__device__ int g_cur[NN];
__device__ int g_eidx[NE];
__device__ int g_bsum[256];
__device__ int g_bo[256];

// ---------------- helpers ----------------
__device__ __forceinline__ unsigned packh2(float a, float b) {
    half2 h = __floats2half2_rn(a, b);
    return *(unsigned*)&h;
}
__device__ __forceinline__ void ldmA(unsigned a[4], unsigned saddr) {
    asm volatile("ldmatrix.sync.aligned.m8n8.x4.shared.b16 {%0,%1,%2,%3}, [%4];"
                 : "=r"(a[0]), "=r"(a[1]), "=r"(a[2]), "=r"(a[3]) : "r"(saddr));
}
__device__ __forceinline__ void mma16(float* d, const unsigned* a, unsigned b0, unsigned b1) {
    asm volatile("mma.sync.aligned.m16n8k16.row.col.f32.f16.f16.f32 "
                 "{%0,%1,%2,%3}, {%4,%5,%6,%7}, {%8,%9}, {%0,%1,%2,%3};"
                 : "+f"(d[0]), "+f"(d[1]), "+f"(d[2]), "+f"(d[3])
                 : "r"(a[0]), "r"(a[1]), "r"(a[2]), "r"(a[3]), "r"(b0), "r"(b1));
}

// ---------------- CSR build (once per launch) ----------------
__global__ void zero_deg() {
    int i = blockIdx.x * blockDim.x + threadIdx.x;
    if (i < NN) g_deg[i] = 0;
}
__global__ void hist_dst(const int* __restrict__ dst) {
    int e = blockIdx.x * blockDim.x + threadIdx.x;
    if (e < NE) atomicAdd(&g_deg[dst[e]], 1);
}
__global__ void scan_block() {
    __shared__ int s[1024];
    int tid = threadIdx.x;
    int n = blockIdx.x * 1024 + tid;
    int v = (n < NN) ? g_deg[n] : 0;
    s[tid] = v;
    __syncthreads();
    for (int o = 1; o < 1024; o <<= 1) {
        int t = (tid >= o) ? s[tid - o] : 0;
        __syncthreads();
        s[tid] += t;
        __syncthreads();
    }
    if (n < NN) g_off[n] = s[tid] - v;     // exclusive
    if (tid == 1023) g_bsum[blockIdx.x] = s[1023];
}
__global__ void scan_bsum() {
    __shared__ int s[256];
    int tid = threadIdx.x;
    int v = (tid < NSB) ? g_bsum[tid] : 0;
    s[tid] = v;
    __syncthreads();
    for (int o = 1; o < 256; o <<= 1) {
        int t = (tid >= o) ? s[tid - o] : 0;
        __syncthreads();
        s[tid] += t;
        __syncthreads();
    }
    if (tid < NSB) g_bo[tid] = s[tid] - v; // exclusive block offsets
}
__global__ void add_off() {
    int n = blockIdx.x * blockDim.x + threadIdx.x;
    if (n < NN) {
        int o = g_off[n] + g_bo[n >> 10];
        g_off[n] = o;
        g_cur[n] = o;
    }
}
__global__ void fill_csr(const int* __restrict__ dst) {
    int e = blockIdx.x * blockDim.x + threadIdx.x;
    if (e < NE) {
        int pos = atomicAdd(&g_cur[dst[e]], 1);
        g_eidx[pos] = e;
    }
}

// ---------------- gather aggregation ----------------
// layer 0: h5[n] = x[n] + sum relu(x[src]+a*ew+eb)   (din=5, 1 thread/node)
__global__ void gather5(const int* __restrict__ esrc, const float* __restrict__ ea,
                        const float* __restrict__ ew, const float* __restrict__ eb,
                        const float* __restrict__ x, float* __restrict__ h5) {
    int n = blockIdx.x * blockDim.x + threadIdx.x;
    if (n >= NN) return;
    float w0 = __ldg(ew + 0), w1 = __ldg(ew + 1), w2 = __ldg(ew + 2),
          w3 = __ldg(ew + 3), w4 = __ldg(ew + 4);
    float c0 = __ldg(eb + 0), c1 = __ldg(eb + 1), c2 = __ldg(eb + 2),
          c3 = __ldg(eb + 3), c4 = __ldg(eb + 4);
    float a0 = __ldg(x + n * IND + 0), a1 = __ldg(x + n * IND + 1),
          a2 = __ldg(x + n * IND + 2), a3 = __ldg(x + n * IND + 3),
          a4 = __ldg(x + n * IND + 4);
    int o = g_off[n], dg = g_deg[n];
    for (int j = 0; j < dg; j++) {
        int e = __ldg(g_eidx + o + j);
        int s = __ldg(esrc + e);
        float a = __ldg(ea + e);
        a0 += fmaxf(__ldg(x + s * IND + 0) + fmaf(a, w0, c0), 0.f);
        a1 += fmaxf(__ldg(x + s * IND + 1) + fmaf(a, w1, c1), 0.f);
        a2 += fmaxf(__ldg(x + s * IND + 2) + fmaf(a, w2, c2), 0.f);
        a3 += fmaxf(__ldg(x + s * IND + 3) + fmaf(a, w3, c3), 0.f);
        a4 += fmaxf(__ldg(x + s * IND + 4) + fmaf(a, w4, c4), 0.f);
    }
    h5[n * IND + 0] = a0; h5[n * IND + 1] = a1; h5[n * IND + 2] = a2;
    h5[n * IND + 3] = a3; h5[n * IND + 4] = a4;
}

// HD layers: h[n] = y[n] + sum relu(y[src]+a*ew+eb). 16 lanes/node, fp32 acc.
__global__ void gather128(const int* __restrict__ esrc, const float* __restrict__ ea,
                          const float* __restrict__ ew, const float* __restrict__ eb,
                          const __half* __restrict__ y, __half* __restrict__ h) {
    int t = blockIdx.x * blockDim.x + threadIdx.x;
    int node = t >> 4;
    if (node >= NN) return;
    int lane = t & 15;
    const float4 w0 = __ldg((const float4*)ew + lane * 2);
    const float4 w1 = __ldg((const float4*)ew + lane * 2 + 1);
    const float4 c0 = __ldg((const float4*)eb + lane * 2);
    const float4 c1 = __ldg((const float4*)eb + lane * 2 + 1);
    uint4 v = __ldg((const uint4*)(y + (size_t)node * HD) + lane);
    float2 b0 = __half22float2(*(half2*)&v.x);
    float2 b1 = __half22float2(*(half2*)&v.y);
    float2 b2 = __half22float2(*(half2*)&v.z);
    float2 b3 = __half22float2(*(half2*)&v.w);
    float acc0 = b0.x, acc1 = b0.y, acc2 = b1.x, acc3 = b1.y;
    float acc4 = b2.x, acc5 = b2.y, acc6 = b3.x, acc7 = b3.y;
    int o = __ldg(g_off + node), dg = __ldg(g_deg + node);
    for (int j = 0; j < dg; j++) {
        int e = __ldg(g_eidx + o + j);
        int s = __ldg(esrc + e);
        float a = __ldg(ea + e);
        uint4 xv = __ldg((const uint4*)(y + (size_t)s * HD) + lane);
        float2 x0 = __half22float2(*(half2*)&xv.x);
        float2 x1 = __half22float2(*(half2*)&xv.y);
        float2 x2 = __half22float2(*(half2*)&xv.z);
        float2 x3 = __half22float2(*(half2*)&xv.w);
        acc0 += fmaxf(x0.x + fmaf(a, w0.x, c0.x), 0.f);
        acc1 += fmaxf(x0.y + fmaf(a, w0.y, c0.y), 0.f);
        acc2 += fmaxf(x1.x + fmaf(a, w0.z, c0.z), 0.f);
        acc3 += fmaxf(x1.y + fmaf(a, w0.w, c0.w), 0.f);
        acc4 += fmaxf(x2.x + fmaf(a, w1.x, c1.x), 0.f);
        acc5 += fmaxf(x2.y + fmaf(a, w1.y, c1.y), 0.f);
        acc6 += fmaxf(x3.x + fmaf(a, w1.z, c1.z), 0.f);
        acc7 += fmaxf(x3.y + fmaf(a, w1.w, c1.w), 0.f);
    }
    uint4 ov;
    ov.x = packh2(acc0, acc1);
    ov.y = packh2(acc2, acc3);
    ov.z = packh2(acc4, acc5);
    ov.w = packh2(acc6, acc7);
    *(uint4*)(h + (size_t)node * HD + lane * 8) = ov;
}

// ---------------- fused MLP + LN, fp16 m16n8k16, persistent ----------------
#define OFF_A   3072
#define OFF_MID (OFF_A + TROWS * SROW * 2)
#define OFF_SP  (OFF_MID + TROWS * SROW * 2)
#define SMEM_TOT (OFF_SP + 2 * TROWS * SPST * 4)
#define NTILE (NN / TROWS)

template <int DIN>
__global__ void __launch_bounds__(256, 2) mlp_tc(
        const void* __restrict__ hin_v,
        const float* __restrict__ w1, const float* __restrict__ b1,
        const float* __restrict__ w2, const float* __restrict__ b2,
        const float* __restrict__ gam, const float* __restrict__ bet,
        __half* __restrict__ out) {
    extern __shared__ char smem[];
    float* s_b1 = (float*)smem;
    float* s_b2 = s_b1 + 128;
    float* s_g  = s_b1 + 256;
    float* s_bt = s_b1 + 384;
    half*  sA   = (half*)(smem + OFF_A);
    half*  sMid = (half*)(smem + OFF_MID);
    float* sp_s = (float*)(smem + OFF_SP);
    float* sp_q = sp_s + TROWS * SPST;

    const int tid = threadIdx.x;
    const int w = tid >> 5, lane = tid & 31;
    const int qr = lane >> 2, qc = lane & 3;
    const int wbase = w * 16;
    const int lm_r = ((lane >> 3) & 1) * 8 + (lane & 7);
    const int lm_c = (lane >> 4) * 8;

    if (tid < 128) {
        s_b1[tid] = __ldg(b1 + tid);
        s_b2[tid] = __ldg(b2 + tid);
        s_g[tid]  = __ldg(gam + tid);
        s_bt[tid] = __ldg(bet + tid);
    }

    constexpr int NKS1 = (DIN == HD) ? 8 : 1;
    unsigned wf1[2][NKS1][2], wf2[2][8][2];
#pragma unroll
    for (int nt = 0; nt < 2; nt++) {
        int n = wbase + nt * 8 + qr;
#pragma unroll
        for (int kk = 0; kk < NKS1; kk++) {
            int k0 = kk * 16 + 2 * qc;
            float f0 = (k0 < DIN)     ? __ldg(w1 + (size_t)k0 * HD + n)       : 0.f;
            float f1 = (k0 + 1 < DIN) ? __ldg(w1 + (size_t)(k0 + 1) * HD + n) : 0.f;
            float f2 = (k0 + 8 < DIN) ? __ldg(w1 + (size_t)(k0 + 8) * HD + n) : 0.f;
            float f3 = (k0 + 9 < DIN) ? __ldg(w1 + (size_t)(k0 + 9) * HD + n) : 0.f;
            wf1[nt][kk][0] = packh2(f0, f1);
            wf1[nt][kk][1] = packh2(f2, f3);
        }
#pragma unroll
        for (int kk = 0; kk < 8; kk++) {
            int k0 = kk * 16 + 2 * qc;
            wf2[nt][kk][0] = packh2(__ldg(w2 + (size_t)k0 * HD + n),
                                    __ldg(w2 + (size_t)(k0 + 1) * HD + n));
            wf2[nt][kk][1] = packh2(__ldg(w2 + (size_t)(k0 + 8) * HD + n),
                                    __ldg(w2 + (size_t)(k0 + 9) * HD + n));
        }
    }
    __syncthreads();

    const unsigned sA_base   = (unsigned)__cvta_generic_to_shared(sA);
    const unsigned sMid_base = (unsigned)__cvta_generic_to_shared(sMid);

    for (int tile = blockIdx.x; tile < NTILE; tile += GRID_P) {
        const int n0 = tile * TROWS;

        if (DIN == HD) {
            const __half* hin = (const __half*)hin_v;
            for (int idx = tid; idx < TROWS * 16; idx += 256) {
                int row = idx >> 4, q = idx & 15;
                uint4 v = __ldg((const uint4*)(hin + (size_t)(n0 + row) * HD) + q);
                *(uint4*)(sA + row * SROW + q * 8) = v;
            }
        } else {
            const float* hin = (const float*)hin_v;
            for (int idx = tid; idx < TROWS * 16; idx += 256) {
                int row = idx >> 4, k = idx & 15;
                float f = (k < IND) ? __ldg(hin + (size_t)(n0 + row) * IND + k) : 0.f;
                sA[row * SROW + k] = __float2half_rn(f);
            }
        }
        __syncthreads();

        // ---- GEMM1 + bias1 + ReLU -> sMid ----
#pragma unroll 1
        for (int mt = 0; mt < TROWS / 16; mt++) {
            float d0[4] = {0, 0, 0, 0}, d1[4] = {0, 0, 0, 0};
            int r0 = mt * 16;
#pragma unroll
            for (int kk = 0; kk < NKS1; kk++) {
                unsigned a[4];
                ldmA(a, sA_base + ((r0 + lm_r) * SROW + kk * 16 + lm_c) * 2);
                mma16(d0, a, wf1[0][kk][0], wf1[0][kk][1]);
                mma16(d1, a, wf1[1][kk][0], wf1[1][kk][1]);
            }
#pragma unroll
            for (int nt = 0; nt < 2; nt++) {
                float* d = nt ? d1 : d0;
                int c0 = wbase + nt * 8 + 2 * qc;
                *(unsigned*)(sMid + (r0 + qr) * SROW + c0) =
                    packh2(fmaxf(d[0] + s_b1[c0], 0.f), fmaxf(d[1] + s_b1[c0 + 1], 0.f));
                *(unsigned*)(sMid + (r0 + 8 + qr) * SROW + c0) =
                    packh2(fmaxf(d[2] + s_b1[c0], 0.f), fmaxf(d[3] + s_b1[c0 + 1], 0.f));
            }
        }
        __syncthreads();

        // ---- GEMM2 + bias2: partial LN sums -> sp, fp16 values -> sA ----
#pragma unroll 1
        for (int mt = 0; mt < TROWS / 16; mt++) {
            float d0[4] = {0, 0, 0, 0}, d1[4] = {0, 0, 0, 0};
            int r0 = mt * 16;
#pragma unroll
            for (int kk = 0; kk < 8; kk++) {
                unsigned a[4];
                ldmA(a, sMid_base + ((r0 + lm_r) * SROW + kk * 16 + lm_c) * 2);
                mma16(d0, a, wf2[0][kk][0], wf2[0][kk][1]);
                mma16(d1, a, wf2[1][kk][0], wf2[1][kk][1]);
            }
            {
                int c0 = wbase + 2 * qc, c1 = wbase + 8 + 2 * qc;
                d0[0] += s_b2[c0]; d0[1] += s_b2[c0 + 1];
                d0[2] += s_b2[c0]; d0[3] += s_b2[c0 + 1];
                d1[0] += s_b2[c1]; d1[1] += s_b2[c1 + 1];
                d1[2] += s_b2[c1]; d1[3] += s_b2[c1 + 1];
            }
            float sa = d0[0] + d0[1] + d1[0] + d1[1];
            float sb = d0[2] + d0[3] + d1[2] + d1[3];
            float qa = d0[0] * d0[0] + d0[1] * d0[1] + d1[0] * d1[0] + d1[1] * d1[1];
            float qb = d0[2] * d0[2] + d0[3] * d0[3] + d1[2] * d1[2] + d1[3] * d1[3];
#pragma unroll
            for (int o = 1; o <= 2; o <<= 1) {
                sa += __shfl_xor_sync(0xffffffffu, sa, o);
                sb += __shfl_xor_sync(0xffffffffu, sb, o);
                qa += __shfl_xor_sync(0xffffffffu, qa, o);
                qb += __shfl_xor_sync(0xffffffffu, qb, o);
            }
            if (qc == 0) {
                sp_s[(r0 + qr) * SPST + w] = sa;
                sp_s[(r0 + 8 + qr) * SPST + w] = sb;
                sp_q[(r0 + qr) * SPST + w] = qa;
                sp_q[(r0 + 8 + qr) * SPST + w] = qb;
            }
            {
                int c0 = wbase + 2 * qc;
                *(unsigned*)(sA + (r0 + qr) * SROW + c0)      = packh2(d0[0], d0[1]);
                *(unsigned*)(sA + (r0 + qr) * SROW + c0 + 8)  = packh2(d1[0], d1[1]);
                *(unsigned*)(sA + (r0 + 8 + qr) * SROW + c0)     = packh2(d0[2], d0[3]);
                *(unsigned*)(sA + (r0 + 8 + qr) * SROW + c0 + 8) = packh2(d1[2], d1[3]);
            }
        }
        __syncthreads();

        // ---- LN apply + ReLU + coalesced fp16 store ----
        for (int idx = tid; idx < TROWS * 16; idx += 256) {
            int row = idx >> 4, q = idx & 15;
            float4 sa = *(const float4*)(sp_s + row * SPST);
            float4 sb = *(const float4*)(sp_s + row * SPST + 4);
            float4 qa = *(const float4*)(sp_q + row * SPST);
            float4 qb = *(const float4*)(sp_q + row * SPST + 4);
            float s  = sa.x + sa.y + sa.z + sa.w + sb.x + sb.y + sb.z + sb.w;
            float s2 = qa.x + qa.y + qa.z + qa.w + qb.x + qb.y + qb.z + qb.w;
            float mean = s * (1.f / HD);
            float var = s2 * (1.f / HD) - mean * mean;
            float rstd = rsqrtf(var + 1e-5f);
            uint4 v = *(const uint4*)(sA + row * SROW + q * 8);
            float2 v0 = __half22float2(*(half2*)&v.x);
            float2 v1 = __half22float2(*(half2*)&v.y);
            float2 v2 = __half22float2(*(half2*)&v.z);
            float2 v3 = __half22float2(*(half2*)&v.w);
            int c = q * 8;
            uint4 o;
            o.x = packh2(fmaxf((v0.x - mean) * rstd * s_g[c + 0] + s_bt[c + 0], 0.f),
                         fmaxf((v0.y - mean) * rstd * s_g[c + 1] + s_bt[c + 1], 0.f));
            o.y = packh2(fmaxf((v1.x - mean) * rstd * s_g[c + 2] + s_bt[c + 2], 0.f),
                         fmaxf((v1.y - mean) * rstd * s_g[c + 3] + s_bt[c + 3], 0.f));
            o.z = packh2(fmaxf((v2.x - mean) * rstd * s_g[c + 4] + s_bt[c + 4], 0.f),
                         fmaxf((v2.y - mean) * rstd * s_g[c + 5] + s_bt[c + 5], 0.f));
            o.w = packh2(fmaxf((v3.x - mean) * rstd * s_g[c + 6] + s_bt[c + 6], 0.f),
                         fmaxf((v3.y - mean) * rstd * s_g[c + 7] + s_bt[c + 7], 0.f));
            *(uint4*)(out + (size_t)(n0 + row) * HD + c) = o;
        }
        __syncthreads();
    }
}

// ---------------- pooling ----------------
__global__ void zero_pool() {
    int i = blockIdx.x * blockDim.x + threadIdx.x;
    if (i < NG * HD) g_pool[i] = 0.f;
    if (i < NG) g_cnt[i] = 0;
}

__global__ void pool128(const __half* __restrict__ x, const int* __restrict__ batch) {
    const int CHUNK = 50;
    int n0 = blockIdx.x * CHUNK;
    int n1 = n0 + CHUNK;
    if (n1 > NN) n1 = NN;
    int j = threadIdx.x;
    float acc = 0.f;
    int cnt = 0;
    int cur = batch[n0];
    for (int n = n0; n < n1; n++) {
        int g = batch[n];
        if (g != cur) {
            atomicAdd(&g_pool[cur * HD + j], acc);
            if (j == 0) atomicAdd(&g_cnt[cur], cnt);
            acc = 0.f; cnt = 0; cur = g;
        }
        acc += __half2float(x[(size_t)n * HD + j]);
        cnt++;
    }
    atomicAdd(&g_pool[cur * HD + j], acc);
    if (j == 0) atomicAdd(&g_cnt[cur], cnt);
}

__global__ void finalize(float* __restrict__ out) {
    int g = blockIdx.x, j = threadIdx.x;
    float s = g_pool[g * HD + j];
    int c = g_cnt[g];
    float cf = (float)(c > 1 ? c : 1);
    out[g * 2 * HD + j]      = s / cf;
    out[g * 2 * HD + HD + j] = s;
}

// ---------------------------------------------------------------------------
extern "C" void kernel_launch(void* const* d_in, const int* in_sizes, int n_in,
                              void* d_out, int out_size) {
    const float* x     = (const float*)d_in[0];
    const int*   ei    = (const int*)d_in[1];
    const float* ea    = (const float*)d_in[2];
    const int*   batch = (const int*)d_in[3];
    const float* P[24];
    for (int i = 0; i < 24; i++) P[i] = (const float*)d_in[4 + i];
    const int* esrc = ei;
    const int* edst = ei + NE;

    float* h5;
    __half *h, *bufA, *bufB;
    cudaGetSymbolAddress((void**)&h5, g_h5);
    cudaGetSymbolAddress((void**)&h, g_h);
    cudaGetSymbolAddress((void**)&bufA, g_bufA);
    cudaGetSymbolAddress((void**)&bufB, g_bufB);

    cudaFuncSetAttribute(mlp_tc<IND>, cudaFuncAttributeMaxDynamicSharedMemorySize, SMEM_TOT);
    cudaFuncSetAttribute(mlp_tc<HD>,  cudaFuncAttributeMaxDynamicSharedMemorySize, SMEM_TOT);

    const int TB = 256;

    // ---- CSR build (once; graph shared by all 3 layers) ----
    zero_deg<<<(NN + TB - 1) / TB, TB>>>();
    hist_dst<<<(NE + TB - 1) / TB, TB>>>(edst);
    scan_block<<<NSB, 1024>>>();
    scan_bsum<<<1, 256>>>();
    add_off<<<(NN + TB - 1) / TB, TB>>>();
    fill_csr<<<(NE + TB - 1) / TB, TB>>>(edst);

    // ---- layer 0 (din = 5) ----
    gather5<<<(NN + TB - 1) / TB, TB>>>(esrc, ea, P[0], P[1], x, h5);
    mlp_tc<IND><<<GRID_P, 256, SMEM_TOT>>>(h5, P[2], P[3], P[4], P[5], P[6], P[7], bufA);

    // ---- layer 1 ----
    gather128<<<NN * 16 / TB, TB>>>(esrc, ea, P[8], P[9], bufA, h);
    mlp_tc<HD><<<GRID_P, 256, SMEM_TOT>>>(h, P[10], P[11], P[12], P[13], P[14], P[15], bufB);

    // ---- layer 2 ----
    gather128<<<NN * 16 / TB, TB>>>(esrc, ea, P[16], P[17], bufB, h);
    mlp_tc<HD><<<GRID_P, 256, SMEM_TOT>>>(h, P[18], P[19], P[20], P[21], P[22], P[23], bufA);

    // ---- pooling ----
    zero_pool<<<(NG * HD + TB - 1) / TB, TB>>>();
    pool128<<<NN / 50, HD>>>(bufA, batch);
    finalize<<<NG, HD>>>((float*)d_out);
}

// round 11
// speedup vs baseline: 1.4391x; 1.4391x over previous
#include <cuda_runtime.h>
#include <cuda_fp16.h>

#define NN 200000
#define NE 400000
#define NG 64
#define HD 128
#define IND 5
#define TROWS 64
#define SROW 136        // f16 tile row stride (halves): ldmatrix conflict-free
#define SPST 12         // partial-sum row stride (floats): 48B, 16B-aligned
#define GRID_P 304      // persistent CTAs (2 per SM)

// ---------------- device scratch (allocation-free rule) ----------------
__device__ float  g_h5[NN * IND];
__device__ __half g_h[(size_t)NN * HD];     // accumulation base (y + aggr), fp16
__device__ __half g_bufA[(size_t)NN * HD];  // layer outputs ping (fp16)
__device__ __half g_bufB[(size_t)NN * HD];  // layer outputs pong (fp16)
__device__ float  g_pool[NG * HD];
__device__ int    g_cnt[NG];

// ---------------- helpers ----------------
__device__ __forceinline__ unsigned packh2(float a, float b) {
    half2 h = __floats2half2_rn(a, b);
    return *(unsigned*)&h;
}
__device__ __forceinline__ void ldmA(unsigned a[4], unsigned saddr) {
    asm volatile("ldmatrix.sync.aligned.m8n8.x4.shared.b16 {%0,%1,%2,%3}, [%4];"
                 : "=r"(a[0]), "=r"(a[1]), "=r"(a[2]), "=r"(a[3]) : "r"(saddr));
}
__device__ __forceinline__ void mma16(float* d, const unsigned* a, unsigned b0, unsigned b1) {
    asm volatile("mma.sync.aligned.m16n8k16.row.col.f32.f16.f16.f32 "
                 "{%0,%1,%2,%3}, {%4,%5,%6,%7}, {%8,%9}, {%0,%1,%2,%3};"
                 : "+f"(d[0]), "+f"(d[1]), "+f"(d[2]), "+f"(d[3])
                 : "r"(a[0]), "r"(a[1]), "r"(a[2]), "r"(a[3]), "r"(b0), "r"(b1));
}
__device__ __forceinline__ void cp_async16(unsigned saddr, const void* gptr) {
    asm volatile("cp.async.cg.shared.global [%0], [%1], 16;" :: "r"(saddr), "l"(gptr));
}
#define CP_COMMIT() asm volatile("cp.async.commit_group;" ::: "memory")
#define CP_WAIT0()  asm volatile("cp.async.wait_group 0;" ::: "memory")

// ---------------- misc small kernels ----------------
__global__ void copy_f(float* __restrict__ dst, const float* __restrict__ src, int n) {
    int i = blockIdx.x * blockDim.x + threadIdx.x;
    if (i < n) dst[i] = src[i];
}

__global__ void edge5(const int* __restrict__ src, const int* __restrict__ dst,
                      const float* __restrict__ ea,
                      const float* __restrict__ ew, const float* __restrict__ eb,
                      const float* __restrict__ x, float* __restrict__ h) {
    int e = blockIdx.x * blockDim.x + threadIdx.x;
    if (e >= NE) return;
    int s = __ldg(src + e), d = __ldg(dst + e);
    float a = __ldg(ea + e);
#pragma unroll
    for (int j = 0; j < IND; j++) {
        float m = fmaxf(__ldg(x + s * IND + j) + fmaf(a, __ldg(ew + j), __ldg(eb + j)), 0.f);
        atomicAdd(&h[d * IND + j], m);
    }
}

// fp16 edge message + scatter. Persistent: lane constants in registers; unroll 2.
__global__ void edge128h(const int* __restrict__ src, const int* __restrict__ dst,
                         const float* __restrict__ ea,
                         const float* __restrict__ ew, const float* __restrict__ eb,
                         const __half* __restrict__ x, __half* __restrict__ h) {
    const int lane = threadIdx.x & 15;        // halves [lane*8, lane*8+8)
    const int g0 = (blockIdx.x * blockDim.x + threadIdx.x) >> 4;
    const int gs = (gridDim.x * blockDim.x) >> 4;
    const float4 w0 = __ldg((const float4*)ew + lane * 2);
    const float4 w1 = __ldg((const float4*)ew + lane * 2 + 1);
    const float4 c0 = __ldg((const float4*)eb + lane * 2);
    const float4 c1 = __ldg((const float4*)eb + lane * 2 + 1);
#pragma unroll 2
    for (int e = g0; e < NE; e += gs) {
        int s = __ldg(src + e), d = __ldg(dst + e);
        float a = __ldg(ea + e);
        uint4 xv = __ldg((const uint4*)(x + (size_t)s * HD) + lane);
        float2 x0 = __half22float2(*(half2*)&xv.x);
        float2 x1 = __half22float2(*(half2*)&xv.y);
        float2 x2 = __half22float2(*(half2*)&xv.z);
        float2 x3 = __half22float2(*(half2*)&xv.w);
        unsigned m0 = packh2(fmaxf(x0.x + fmaf(a, w0.x, c0.x), 0.f),
                             fmaxf(x0.y + fmaf(a, w0.y, c0.y), 0.f));
        unsigned m1 = packh2(fmaxf(x1.x + fmaf(a, w0.z, c0.z), 0.f),
                             fmaxf(x1.y + fmaf(a, w0.w, c0.w), 0.f));
        unsigned m2 = packh2(fmaxf(x2.x + fmaf(a, w1.x, c1.x), 0.f),
                             fmaxf(x2.y + fmaf(a, w1.y, c1.y), 0.f));
        unsigned m3 = packh2(fmaxf(x3.x + fmaf(a, w1.z, c1.z), 0.f),
                             fmaxf(x3.y + fmaf(a, w1.w, c1.w), 0.f));
        __half* p = h + (size_t)d * HD + lane * 8;
        asm volatile("red.global.add.noftz.v4.f16x2 [%0], {%1, %2, %3, %4};"
                     :: "l"(p), "r"(m0), "r"(m1), "r"(m2), "r"(m3) : "memory");
    }
}

// ---------------- fused MLP + LN, fp16 m16n8k16, persistent, cp.async pipelined ----------------
// smem (bytes): [0,3072) params | sA0 | sA1 | sMid | sp
#define TILEB   (TROWS * SROW * 2)         // 17408
#define OFF_A0  3072
#define OFF_A1  (OFF_A0 + TILEB)
#define OFF_MID (OFF_A1 + TILEB)
#define OFF_SP  (OFF_MID + TILEB)
#define SMEM_TOT (OFF_SP + 2 * TROWS * SPST * 4)
#define NTILE (NN / TROWS)

template <int DIN, bool DUAL>
__global__ void __launch_bounds__(256, 2) mlp_tc(
        const void* __restrict__ hin_v,
        const float* __restrict__ w1, const float* __restrict__ b1,
        const float* __restrict__ w2, const float* __restrict__ b2,
        const float* __restrict__ gam, const float* __restrict__ bet,
        __half* __restrict__ out, __half* __restrict__ hdup) {
    extern __shared__ char smem[];
    float* s_b1 = (float*)smem;
    float* s_b2 = s_b1 + 128;
    float* s_g  = s_b1 + 256;
    float* s_bt = s_b1 + 384;
    half*  sA0  = (half*)(smem + OFF_A0);
    half*  sA1  = (half*)(smem + OFF_A1);
    half*  sMid = (half*)(smem + OFF_MID);
    float* sp_s = (float*)(smem + OFF_SP);
    float* sp_q = sp_s + TROWS * SPST;

    const int tid = threadIdx.x;
    const int w = tid >> 5, lane = tid & 31;
    const int qr = lane >> 2, qc = lane & 3;
    const int wbase = w * 16;
    const int lm_r = ((lane >> 3) & 1) * 8 + (lane & 7);
    const int lm_c = (lane >> 4) * 8;

    if (tid < 128) {
        s_b1[tid] = __ldg(b1 + tid);
        s_b2[tid] = __ldg(b2 + tid);
        s_g[tid]  = __ldg(gam + tid);
        s_bt[tid] = __ldg(bet + tid);
    }

    // ---- W fragments: loaded ONCE per persistent CTA ----
    constexpr int NKS1 = (DIN == HD) ? 8 : 1;
    unsigned wf1[2][NKS1][2], wf2[2][8][2];
#pragma unroll
    for (int nt = 0; nt < 2; nt++) {
        int n = wbase + nt * 8 + qr;
#pragma unroll
        for (int kk = 0; kk < NKS1; kk++) {
            int k0 = kk * 16 + 2 * qc;
            float f0 = (k0 < DIN)     ? __ldg(w1 + (size_t)k0 * HD + n)       : 0.f;
            float f1 = (k0 + 1 < DIN) ? __ldg(w1 + (size_t)(k0 + 1) * HD + n) : 0.f;
            float f2 = (k0 + 8 < DIN) ? __ldg(w1 + (size_t)(k0 + 8) * HD + n) : 0.f;
            float f3 = (k0 + 9 < DIN) ? __ldg(w1 + (size_t)(k0 + 9) * HD + n) : 0.f;
            wf1[nt][kk][0] = packh2(f0, f1);
            wf1[nt][kk][1] = packh2(f2, f3);
        }
#pragma unroll
        for (int kk = 0; kk < 8; kk++) {
            int k0 = kk * 16 + 2 * qc;
            wf2[nt][kk][0] = packh2(__ldg(w2 + (size_t)k0 * HD + n),
                                    __ldg(w2 + (size_t)(k0 + 1) * HD + n));
            wf2[nt][kk][1] = packh2(__ldg(w2 + (size_t)(k0 + 8) * HD + n),
                                    __ldg(w2 + (size_t)(k0 + 9) * HD + n));
        }
    }
    __syncthreads();

    const unsigned sMid_base = (unsigned)__cvta_generic_to_shared(sMid);
    const unsigned sA0_base  = (unsigned)__cvta_generic_to_shared(sA0);
    const unsigned sA1_base  = (unsigned)__cvta_generic_to_shared(sA1);

    int pb = 0;
    if (DIN == HD) {
        // prime: prefetch first tile into sA0
        const __half* hin = (const __half*)hin_v;
        int n0 = blockIdx.x * TROWS;
#pragma unroll
        for (int i = 0; i < 4; i++) {
            int idx = tid + i * 256;
            int row = idx >> 4, q = idx & 15;
            cp_async16(sA0_base + (row * SROW + q * 8) * 2,
                       hin + (size_t)(n0 + row) * HD + q * 8);
        }
        CP_COMMIT();
    }

    for (int tile = blockIdx.x; tile < NTILE; tile += GRID_P) {
        const int n0 = tile * TROWS;
        half* sAc = pb ? sA1 : sA0;
        const unsigned sAc_base = pb ? sA1_base : sA0_base;

        if (DIN == HD) {
            CP_WAIT0();
            __syncthreads();                 // A_t visible to all; prev LN apply done
            int tn = tile + GRID_P;
            if (tn < NTILE) {                // prefetch next tile into alternate buf
                const __half* hin = (const __half*)hin_v;
                const unsigned sAn_base = pb ? sA0_base : sA1_base;
                int m0 = tn * TROWS;
#pragma unroll
                for (int i = 0; i < 4; i++) {
                    int idx = tid + i * 256;
                    int row = idx >> 4, q = idx & 15;
                    cp_async16(sAn_base + (row * SROW + q * 8) * 2,
                               (const __half*)hin_v + (size_t)(m0 + row) * HD + q * 8);
                }
            }
            CP_COMMIT();
        } else {
            const float* hin = (const float*)hin_v;
            for (int idx = tid; idx < TROWS * 16; idx += 256) {
                int row = idx >> 4, k = idx & 15;
                float f = (k < IND) ? __ldg(hin + (size_t)(n0 + row) * IND + k) : 0.f;
                sAc[row * SROW + k] = __float2half_rn(f);
            }
            __syncthreads();
        }

        // ---- GEMM1 + bias1 + ReLU -> sMid ----
#pragma unroll 1
        for (int mt = 0; mt < TROWS / 16; mt++) {
            float d0[4] = {0, 0, 0, 0}, d1[4] = {0, 0, 0, 0};
            int r0 = mt * 16;
#pragma unroll
            for (int kk = 0; kk < NKS1; kk++) {
                unsigned a[4];
                ldmA(a, sAc_base + ((r0 + lm_r) * SROW + kk * 16 + lm_c) * 2);
                mma16(d0, a, wf1[0][kk][0], wf1[0][kk][1]);
                mma16(d1, a, wf1[1][kk][0], wf1[1][kk][1]);
            }
#pragma unroll
            for (int nt = 0; nt < 2; nt++) {
                float* d = nt ? d1 : d0;
                int c0 = wbase + nt * 8 + 2 * qc;
                *(unsigned*)(sMid + (r0 + qr) * SROW + c0) =
                    packh2(fmaxf(d[0] + s_b1[c0], 0.f), fmaxf(d[1] + s_b1[c0 + 1], 0.f));
                *(unsigned*)(sMid + (r0 + 8 + qr) * SROW + c0) =
                    packh2(fmaxf(d[2] + s_b1[c0], 0.f), fmaxf(d[3] + s_b1[c0 + 1], 0.f));
            }
        }
        __syncthreads();

        // ---- GEMM2 + bias2: partial LN sums -> sp, fp16 values -> sAc ----
#pragma unroll 1
        for (int mt = 0; mt < TROWS / 16; mt++) {
            float d0[4] = {0, 0, 0, 0}, d1[4] = {0, 0, 0, 0};
            int r0 = mt * 16;
#pragma unroll
            for (int kk = 0; kk < 8; kk++) {
                unsigned a[4];
                ldmA(a, sMid_base + ((r0 + lm_r) * SROW + kk * 16 + lm_c) * 2);
                mma16(d0, a, wf2[0][kk][0], wf2[0][kk][1]);
                mma16(d1, a, wf2[1][kk][0], wf2[1][kk][1]);
            }
            {
                int c0 = wbase + 2 * qc, c1 = wbase + 8 + 2 * qc;
                d0[0] += s_b2[c0]; d0[1] += s_b2[c0 + 1];
                d0[2] += s_b2[c0]; d0[3] += s_b2[c0 + 1];
                d1[0] += s_b2[c1]; d1[1] += s_b2[c1 + 1];
                d1[2] += s_b2[c1]; d1[3] += s_b2[c1 + 1];
            }
            float sa = d0[0] + d0[1] + d1[0] + d1[1];
            float sb = d0[2] + d0[3] + d1[2] + d1[3];
            float qa = d0[0] * d0[0] + d0[1] * d0[1] + d1[0] * d1[0] + d1[1] * d1[1];
            float qb = d0[2] * d0[2] + d0[3] * d0[3] + d1[2] * d1[2] + d1[3] * d1[3];
#pragma unroll
            for (int o = 1; o <= 2; o <<= 1) {
                sa += __shfl_xor_sync(0xffffffffu, sa, o);
                sb += __shfl_xor_sync(0xffffffffu, sb, o);
                qa += __shfl_xor_sync(0xffffffffu, qa, o);
                qb += __shfl_xor_sync(0xffffffffu, qb, o);
            }
            if (qc == 0) {
                sp_s[(r0 + qr) * SPST + w] = sa;
                sp_s[(r0 + 8 + qr) * SPST + w] = sb;
                sp_q[(r0 + qr) * SPST + w] = qa;
                sp_q[(r0 + 8 + qr) * SPST + w] = qb;
            }
            {
                int c0 = wbase + 2 * qc;
                *(unsigned*)(sAc + (r0 + qr) * SROW + c0)      = packh2(d0[0], d0[1]);
                *(unsigned*)(sAc + (r0 + qr) * SROW + c0 + 8)  = packh2(d1[0], d1[1]);
                *(unsigned*)(sAc + (r0 + 8 + qr) * SROW + c0)     = packh2(d0[2], d0[3]);
                *(unsigned*)(sAc + (r0 + 8 + qr) * SROW + c0 + 8) = packh2(d1[2], d1[3]);
            }
        }
        __syncthreads();

        // ---- LN apply + ReLU + coalesced fp16 store (dual) ----
        for (int idx = tid; idx < TROWS * 16; idx += 256) {
            int row = idx >> 4, q = idx & 15;
            float4 sa = *(const float4*)(sp_s + row * SPST);
            float4 sb = *(const float4*)(sp_s + row * SPST + 4);
            float4 qa = *(const float4*)(sp_q + row * SPST);
            float4 qb = *(const float4*)(sp_q + row * SPST + 4);
            float s  = sa.x + sa.y + sa.z + sa.w + sb.x + sb.y + sb.z + sb.w;
            float s2 = qa.x + qa.y + qa.z + qa.w + qb.x + qb.y + qb.z + qb.w;
            float mean = s * (1.f / HD);
            float var = s2 * (1.f / HD) - mean * mean;
            float rstd = rsqrtf(var + 1e-5f);
            uint4 v = *(const uint4*)(sAc + row * SROW + q * 8);
            float2 v0 = __half22float2(*(half2*)&v.x);
            float2 v1 = __half22float2(*(half2*)&v.y);
            float2 v2 = __half22float2(*(half2*)&v.z);
            float2 v3 = __half22float2(*(half2*)&v.w);
            int c = q * 8;
            uint4 o;
            o.x = packh2(fmaxf((v0.x - mean) * rstd * s_g[c + 0] + s_bt[c + 0], 0.f),
                         fmaxf((v0.y - mean) * rstd * s_g[c + 1] + s_bt[c + 1], 0.f));
            o.y = packh2(fmaxf((v1.x - mean) * rstd * s_g[c + 2] + s_bt[c + 2], 0.f),
                         fmaxf((v1.y - mean) * rstd * s_g[c + 3] + s_bt[c + 3], 0.f));
            o.z = packh2(fmaxf((v2.x - mean) * rstd * s_g[c + 4] + s_bt[c + 4], 0.f),
                         fmaxf((v2.y - mean) * rstd * s_g[c + 5] + s_bt[c + 5], 0.f));
            o.w = packh2(fmaxf((v3.x - mean) * rstd * s_g[c + 6] + s_bt[c + 6], 0.f),
                         fmaxf((v3.y - mean) * rstd * s_g[c + 7] + s_bt[c + 7], 0.f));
            size_t off = (size_t)(n0 + row) * HD + c;
            *(uint4*)(out + off) = o;
            if (DUAL) *(uint4*)(hdup + off) = o;
        }
        pb ^= 1;
    }
}

// ---------------- pooling ----------------
__global__ void zero_pool() {
    int i = blockIdx.x * blockDim.x + threadIdx.x;
    if (i < NG * HD) g_pool[i] = 0.f;
    if (i < NG) g_cnt[i] = 0;
}

__global__ void pool128(const __half* __restrict__ x, const int* __restrict__ batch) {
    const int CHUNK = 50;
    int n0 = blockIdx.x * CHUNK;
    int n1 = n0 + CHUNK;
    if (n1 > NN) n1 = NN;
    int j = threadIdx.x;
    float acc = 0.f;
    int cnt = 0;
    int cur = batch[n0];
    for (int n = n0; n < n1; n++) {
        int g = batch[n];
        if (g != cur) {
            atomicAdd(&g_pool[cur * HD + j], acc);
            if (j == 0) atomicAdd(&g_cnt[cur], cnt);
            acc = 0.f; cnt = 0; cur = g;
        }
        acc += __half2float(x[(size_t)n * HD + j]);
        cnt++;
    }
    atomicAdd(&g_pool[cur * HD + j], acc);
    if (j == 0) atomicAdd(&g_cnt[cur], cnt);
}

__global__ void finalize(float* __restrict__ out) {
    int g = blockIdx.x, j = threadIdx.x;
    float s = g_pool[g * HD + j];
    int c = g_cnt[g];
    float cf = (float)(c > 1 ? c : 1);
    out[g * 2 * HD + j]      = s / cf;
    out[g * 2 * HD + HD + j] = s;
}

// ---------------------------------------------------------------------------
extern "C" void kernel_launch(void* const* d_in, const int* in_sizes, int n_in,
                              void* d_out, int out_size) {
    const float* x     = (const float*)d_in[0];
    const int*   ei    = (const int*)d_in[1];
    const float* ea    = (const float*)d_in[2];
    const int*   batch = (const int*)d_in[3];
    const float* P[24];
    for (int i = 0; i < 24; i++) P[i] = (const float*)d_in[4 + i];
    const int* esrc = ei;
    const int* edst = ei + NE;

    float* h5;
    __half *h, *bufA, *bufB;
    cudaGetSymbolAddress((void**)&h5, g_h5);
    cudaGetSymbolAddress((void**)&h, g_h);
    cudaGetSymbolAddress((void**)&bufA, g_bufA);
    cudaGetSymbolAddress((void**)&bufB, g_bufB);

    cudaFuncSetAttribute(mlp_tc<IND, true>, cudaFuncAttributeMaxDynamicSharedMemorySize, SMEM_TOT);
    cudaFuncSetAttribute(mlp_tc<HD, true>,  cudaFuncAttributeMaxDynamicSharedMemorySize, SMEM_TOT);
    cudaFuncSetAttribute(mlp_tc<HD, false>, cudaFuncAttributeMaxDynamicSharedMemorySize, SMEM_TOT);

    const int TB = 256;
    const int GEDGE = 3125;   // 3125*256/16 = 50000 edge slots, 8 iters

    // ---- layer 0 (din = 5) ----
    copy_f<<<(NN * IND + TB - 1) / TB, TB>>>(h5, x, NN * IND);
    edge5<<<(NE + TB - 1) / TB, TB>>>(esrc, edst, ea, P[0], P[1], x, h5);
    mlp_tc<IND, true><<<GRID_P, 256, SMEM_TOT>>>(h5, P[2], P[3], P[4], P[5], P[6], P[7], bufA, h);

    // ---- layer 1 ----
    edge128h<<<GEDGE, TB>>>(esrc, edst, ea, P[8], P[9], bufA, h);
    mlp_tc<HD, true><<<GRID_P, 256, SMEM_TOT>>>(h, P[10], P[11], P[12], P[13], P[14], P[15], bufB, h);

    // ---- layer 2 ----
    edge128h<<<GEDGE, TB>>>(esrc, edst, ea, P[16], P[17], bufB, h);
    mlp_tc<HD, false><<<GRID_P, 256, SMEM_TOT>>>(h, P[18], P[19], P[20], P[21], P[22], P[23], bufA, nullptr);

    // ---- pooling ----
    zero_pool<<<(NG * HD + TB - 1) / TB, TB>>>();
    pool128<<<NN / 50, HD>>>(bufA, batch);
    finalize<<<NG, HD>>>((float*)d_out);
}

// round 12
// speedup vs baseline: 1.4920x; 1.0367x over previous
#include <cuda_runtime.h>
#include <cuda_fp16.h>

#define NN 200000
#define NE 400000
#define NG 64
#define HD 128
#define IND 5
#define L0W 16          // layer-0 padded row width (halves)
#define TROWS 64
#define SROW 136        // f16 tile row stride (halves): ldmatrix conflict-free
#define SPST 12         // partial-sum row stride (floats): 48B, 16B-aligned
#define GRID_P 304      // persistent CTAs (2 per SM, 152 SMs)

// ---------------- device scratch (allocation-free rule) ----------------
__device__ __half g_h5h[(size_t)NN * L0W];  // layer-0 padded fp16 (x + aggr)
__device__ __half g_h[(size_t)NN * HD];     // accumulation base (y + aggr), fp16
__device__ __half g_bufA[(size_t)NN * HD];  // layer outputs ping (fp16)
__device__ __half g_bufB[(size_t)NN * HD];  // layer outputs pong (fp16)
__device__ float  g_pool[NG * HD];
__device__ int    g_cnt[NG];

// ---------------- helpers ----------------
__device__ __forceinline__ unsigned packh2(float a, float b) {
    half2 h = __floats2half2_rn(a, b);
    return *(unsigned*)&h;
}
__device__ __forceinline__ void ldmA(unsigned a[4], unsigned saddr) {
    asm volatile("ldmatrix.sync.aligned.m8n8.x4.shared.b16 {%0,%1,%2,%3}, [%4];"
                 : "=r"(a[0]), "=r"(a[1]), "=r"(a[2]), "=r"(a[3]) : "r"(saddr));
}
__device__ __forceinline__ void mma16(float* d, const unsigned* a, unsigned b0, unsigned b1) {
    asm volatile("mma.sync.aligned.m16n8k16.row.col.f32.f16.f16.f32 "
                 "{%0,%1,%2,%3}, {%4,%5,%6,%7}, {%8,%9}, {%0,%1,%2,%3};"
                 : "+f"(d[0]), "+f"(d[1]), "+f"(d[2]), "+f"(d[3])
                 : "r"(a[0]), "r"(a[1]), "r"(a[2]), "r"(a[3]), "r"(b0), "r"(b1));
}
__device__ __forceinline__ void cp_async16(unsigned saddr, const void* gptr) {
    asm volatile("cp.async.cg.shared.global [%0], [%1], 16;" :: "r"(saddr), "l"(gptr));
}
#define CP_COMMIT() asm volatile("cp.async.commit_group;" ::: "memory")
#define CP_WAIT0()  asm volatile("cp.async.wait_group 0;" ::: "memory")

// ---------------- layer-0 prep ----------------
// x [NN,5] fp32 -> padded fp16 [NN,16]
__global__ void copy5h(const float* __restrict__ x, __half* __restrict__ h) {
    int n = blockIdx.x * blockDim.x + threadIdx.x;
    if (n >= NN) return;
    __half v[16];
#pragma unroll
    for (int j = 0; j < L0W; j++)
        v[j] = __float2half_rn(j < IND ? __ldg(x + n * IND + j) : 0.f);
    *(uint4*)(g_h5h + (size_t)n * L0W)     = *(uint4*)v;
    *(uint4*)(g_h5h + (size_t)n * L0W + 8) = *(uint4*)(v + 8);
    (void)h;
}

// layer-0 edge scatter: fp32 message compute, fp16 RED (3 lanes/edge)
__global__ void edge5h(const int* __restrict__ src, const int* __restrict__ dst,
                       const float* __restrict__ ea,
                       const float* __restrict__ ew, const float* __restrict__ eb,
                       const float* __restrict__ x) {
    int e = blockIdx.x * blockDim.x + threadIdx.x;
    if (e >= NE) return;
    int s = __ldg(src + e), d = __ldg(dst + e);
    float a = __ldg(ea + e);
    float m[IND];
#pragma unroll
    for (int j = 0; j < IND; j++)
        m[j] = fmaxf(__ldg(x + s * IND + j) + fmaf(a, __ldg(ew + j), __ldg(eb + j)), 0.f);
    unsigned p0 = packh2(m[0], m[1]);
    unsigned p1 = packh2(m[2], m[3]);
    __half h4 = __float2half_rn(m[4]);
    __half* pd = g_h5h + (size_t)d * L0W;
    asm volatile("red.global.add.noftz.v2.f16x2 [%0], {%1, %2};"
                 :: "l"(pd), "r"(p0), "r"(p1) : "memory");
    asm volatile("red.global.add.noftz.f16 [%0], %1;"
                 :: "l"(pd + 4), "h"(*(unsigned short*)&h4) : "memory");
}

// fp16 edge message + scatter (HD layers). Persistent; lane constants in regs.
__global__ void edge128h(const int* __restrict__ src, const int* __restrict__ dst,
                         const float* __restrict__ ea,
                         const float* __restrict__ ew, const float* __restrict__ eb,
                         const __half* __restrict__ x, __half* __restrict__ h) {
    const int lane = threadIdx.x & 15;        // halves [lane*8, lane*8+8)
    const int g0 = (blockIdx.x * blockDim.x + threadIdx.x) >> 4;
    const int gs = (gridDim.x * blockDim.x) >> 4;
    const float4 w0 = __ldg((const float4*)ew + lane * 2);
    const float4 w1 = __ldg((const float4*)ew + lane * 2 + 1);
    const float4 c0 = __ldg((const float4*)eb + lane * 2);
    const float4 c1 = __ldg((const float4*)eb + lane * 2 + 1);
#pragma unroll 2
    for (int e = g0; e < NE; e += gs) {
        int s = __ldg(src + e), d = __ldg(dst + e);
        float a = __ldg(ea + e);
        uint4 xv = __ldg((const uint4*)(x + (size_t)s * HD) + lane);
        float2 x0 = __half22float2(*(half2*)&xv.x);
        float2 x1 = __half22float2(*(half2*)&xv.y);
        float2 x2 = __half22float2(*(half2*)&xv.z);
        float2 x3 = __half22float2(*(half2*)&xv.w);
        unsigned m0 = packh2(fmaxf(x0.x + fmaf(a, w0.x, c0.x), 0.f),
                             fmaxf(x0.y + fmaf(a, w0.y, c0.y), 0.f));
        unsigned m1 = packh2(fmaxf(x1.x + fmaf(a, w0.z, c0.z), 0.f),
                             fmaxf(x1.y + fmaf(a, w0.w, c0.w), 0.f));
        unsigned m2 = packh2(fmaxf(x2.x + fmaf(a, w1.x, c1.x), 0.f),
                             fmaxf(x2.y + fmaf(a, w1.y, c1.y), 0.f));
        unsigned m3 = packh2(fmaxf(x3.x + fmaf(a, w1.z, c1.z), 0.f),
                             fmaxf(x3.y + fmaf(a, w1.w, c1.w), 0.f));
        __half* p = h + (size_t)d * HD + lane * 8;
        asm volatile("red.global.add.noftz.v4.f16x2 [%0], {%1, %2, %3, %4};"
                     :: "l"(p), "r"(m0), "r"(m1), "r"(m2), "r"(m3) : "memory");
    }
}

// ---------------- fused MLP + LN, fp16 m16n8k16, persistent, cp.async pipelined ----------------
// smem (bytes): [0,3072) params | sA0 | sA1 | sMid | sp
#define TILEB   (TROWS * SROW * 2)         // 17408
#define OFF_A0  3072
#define OFF_A1  (OFF_A0 + TILEB)
#define OFF_MID (OFF_A1 + TILEB)
#define OFF_SP  (OFF_MID + TILEB)
#define SMEM_TOT (OFF_SP + 2 * TROWS * SPST * 4)
#define NTILE (NN / TROWS)

template <int DIN, bool DUAL>
__global__ void __launch_bounds__(256, 2) mlp_tc(
        const __half* __restrict__ hin,
        const float* __restrict__ w1, const float* __restrict__ b1,
        const float* __restrict__ w2, const float* __restrict__ b2,
        const float* __restrict__ gam, const float* __restrict__ bet,
        __half* __restrict__ out, __half* __restrict__ hdup) {
    extern __shared__ char smem[];
    float* s_b1 = (float*)smem;
    float* s_b2 = s_b1 + 128;
    float* s_g  = s_b1 + 256;
    float* s_bt = s_b1 + 384;
    half*  sA0  = (half*)(smem + OFF_A0);
    half*  sA1  = (half*)(smem + OFF_A1);
    half*  sMid = (half*)(smem + OFF_MID);
    float* sp_s = (float*)(smem + OFF_SP);
    float* sp_q = sp_s + TROWS * SPST;

    const int tid = threadIdx.x;
    const int w = tid >> 5, lane = tid & 31;
    const int qr = lane >> 2, qc = lane & 3;
    const int wbase = w * 16;
    const int lm_r = ((lane >> 3) & 1) * 8 + (lane & 7);
    const int lm_c = (lane >> 4) * 8;
    // A-row width in 8-half groups: 2 for layer 0 (16 halves), 16 for HD
    constexpr int NCP = (DIN == HD) ? 16 : 2;

    if (tid < 128) {
        s_b1[tid] = __ldg(b1 + tid);
        s_b2[tid] = __ldg(b2 + tid);
        s_g[tid]  = __ldg(gam + tid);
        s_bt[tid] = __ldg(bet + tid);
    }

    // ---- W fragments: loaded ONCE per persistent CTA ----
    constexpr int NKS1 = (DIN == HD) ? 8 : 1;
    unsigned wf1[2][NKS1][2], wf2[2][8][2];
#pragma unroll
    for (int nt = 0; nt < 2; nt++) {
        int n = wbase + nt * 8 + qr;
#pragma unroll
        for (int kk = 0; kk < NKS1; kk++) {
            int k0 = kk * 16 + 2 * qc;
            float f0 = (k0 < DIN)     ? __ldg(w1 + (size_t)k0 * HD + n)       : 0.f;
            float f1 = (k0 + 1 < DIN) ? __ldg(w1 + (size_t)(k0 + 1) * HD + n) : 0.f;
            float f2 = (k0 + 8 < DIN) ? __ldg(w1 + (size_t)(k0 + 8) * HD + n) : 0.f;
            float f3 = (k0 + 9 < DIN) ? __ldg(w1 + (size_t)(k0 + 9) * HD + n) : 0.f;
            wf1[nt][kk][0] = packh2(f0, f1);
            wf1[nt][kk][1] = packh2(f2, f3);
        }
#pragma unroll
        for (int kk = 0; kk < 8; kk++) {
            int k0 = kk * 16 + 2 * qc;
            wf2[nt][kk][0] = packh2(__ldg(w2 + (size_t)k0 * HD + n),
                                    __ldg(w2 + (size_t)(k0 + 1) * HD + n));
            wf2[nt][kk][1] = packh2(__ldg(w2 + (size_t)(k0 + 8) * HD + n),
                                    __ldg(w2 + (size_t)(k0 + 9) * HD + n));
        }
    }
    __syncthreads();

    const unsigned sMid_base = (unsigned)__cvta_generic_to_shared(sMid);
    const unsigned sA0_base  = (unsigned)__cvta_generic_to_shared(sA0);
    const unsigned sA1_base  = (unsigned)__cvta_generic_to_shared(sA1);

    // prime: prefetch first tile into sA0
    int pb = 0;
    {
        int n0 = blockIdx.x * TROWS;
        for (int idx = tid; idx < TROWS * NCP; idx += 256) {
            int row = idx / NCP, q = idx % NCP;
            cp_async16(sA0_base + (row * SROW + q * 8) * 2,
                       hin + (size_t)(n0 + row) * (NCP * 8) + q * 8);
        }
        CP_COMMIT();
    }

    for (int tile = blockIdx.x; tile < NTILE; tile += GRID_P) {
        const int n0 = tile * TROWS;
        half* sAc = pb ? sA1 : sA0;
        const unsigned sAc_base = pb ? sA1_base : sA0_base;

        CP_WAIT0();
        __syncthreads();                 // A_t visible; prev LN apply done
        int tn = tile + GRID_P;
        if (tn < NTILE) {                // prefetch next tile into alternate buf
            const unsigned sAn_base = pb ? sA0_base : sA1_base;
            int m0 = tn * TROWS;
            for (int idx = tid; idx < TROWS * NCP; idx += 256) {
                int row = idx / NCP, q = idx % NCP;
                cp_async16(sAn_base + (row * SROW + q * 8) * 2,
                           hin + (size_t)(m0 + row) * (NCP * 8) + q * 8);
            }
        }
        CP_COMMIT();

        // ---- GEMM1 + bias1 + ReLU -> sMid ----
#pragma unroll 1
        for (int mt = 0; mt < TROWS / 16; mt++) {
            float d0[4] = {0, 0, 0, 0}, d1[4] = {0, 0, 0, 0};
            int r0 = mt * 16;
#pragma unroll
            for (int kk = 0; kk < NKS1; kk++) {
                unsigned a[4];
                ldmA(a, sAc_base + ((r0 + lm_r) * SROW + kk * 16 + lm_c) * 2);
                mma16(d0, a, wf1[0][kk][0], wf1[0][kk][1]);
                mma16(d1, a, wf1[1][kk][0], wf1[1][kk][1]);
            }
#pragma unroll
            for (int nt = 0; nt < 2; nt++) {
                float* d = nt ? d1 : d0;
                int c0 = wbase + nt * 8 + 2 * qc;
                *(unsigned*)(sMid + (r0 + qr) * SROW + c0) =
                    packh2(fmaxf(d[0] + s_b1[c0], 0.f), fmaxf(d[1] + s_b1[c0 + 1], 0.f));
                *(unsigned*)(sMid + (r0 + 8 + qr) * SROW + c0) =
                    packh2(fmaxf(d[2] + s_b1[c0], 0.f), fmaxf(d[3] + s_b1[c0 + 1], 0.f));
            }
        }
        __syncthreads();

        // ---- GEMM2 + bias2: partial LN sums -> sp, fp16 values -> sAc ----
#pragma unroll 1
        for (int mt = 0; mt < TROWS / 16; mt++) {
            float d0[4] = {0, 0, 0, 0}, d1[4] = {0, 0, 0, 0};
            int r0 = mt * 16;
#pragma unroll
            for (int kk = 0; kk < 8; kk++) {
                unsigned a[4];
                ldmA(a, sMid_base + ((r0 + lm_r) * SROW + kk * 16 + lm_c) * 2);
                mma16(d0, a, wf2[0][kk][0], wf2[0][kk][1]);
                mma16(d1, a, wf2[1][kk][0], wf2[1][kk][1]);
            }
            {
                int c0 = wbase + 2 * qc, c1 = wbase + 8 + 2 * qc;
                d0[0] += s_b2[c0]; d0[1] += s_b2[c0 + 1];
                d0[2] += s_b2[c0]; d0[3] += s_b2[c0 + 1];
                d1[0] += s_b2[c1]; d1[1] += s_b2[c1 + 1];
                d1[2] += s_b2[c1]; d1[3] += s_b2[c1 + 1];
            }
            float sa = d0[0] + d0[1] + d1[0] + d1[1];
            float sb = d0[2] + d0[3] + d1[2] + d1[3];
            float qa = d0[0] * d0[0] + d0[1] * d0[1] + d1[0] * d1[0] + d1[1] * d1[1];
            float qb = d0[2] * d0[2] + d0[3] * d0[3] + d1[2] * d1[2] + d1[3] * d1[3];
#pragma unroll
            for (int o = 1; o <= 2; o <<= 1) {
                sa += __shfl_xor_sync(0xffffffffu, sa, o);
                sb += __shfl_xor_sync(0xffffffffu, sb, o);
                qa += __shfl_xor_sync(0xffffffffu, qa, o);
                qb += __shfl_xor_sync(0xffffffffu, qb, o);
            }
            if (qc == 0) {
                sp_s[(r0 + qr) * SPST + w] = sa;
                sp_s[(r0 + 8 + qr) * SPST + w] = sb;
                sp_q[(r0 + qr) * SPST + w] = qa;
                sp_q[(r0 + 8 + qr) * SPST + w] = qb;
            }
            {
                int c0 = wbase + 2 * qc;
                *(unsigned*)(sAc + (r0 + qr) * SROW + c0)      = packh2(d0[0], d0[1]);
                *(unsigned*)(sAc + (r0 + qr) * SROW + c0 + 8)  = packh2(d1[0], d1[1]);
                *(unsigned*)(sAc + (r0 + 8 + qr) * SROW + c0)     = packh2(d0[2], d0[3]);
                *(unsigned*)(sAc + (r0 + 8 + qr) * SROW + c0 + 8) = packh2(d1[2], d1[3]);
            }
        }
        __syncthreads();

        // ---- LN apply + ReLU + coalesced fp16 store (dual) ----
        for (int idx = tid; idx < TROWS * 16; idx += 256) {
            int row = idx >> 4, q = idx & 15;
            float4 sa = *(const float4*)(sp_s + row * SPST);
            float4 sb = *(const float4*)(sp_s + row * SPST + 4);
            float4 qa = *(const float4*)(sp_q + row * SPST);
            float4 qb = *(const float4*)(sp_q + row * SPST + 4);
            float s  = sa.x + sa.y + sa.z + sa.w + sb.x + sb.y + sb.z + sb.w;
            float s2 = qa.x + qa.y + qa.z + qa.w + qb.x + qb.y + qb.z + qb.w;
            float mean = s * (1.f / HD);
            float var = s2 * (1.f / HD) - mean * mean;
            float rstd = rsqrtf(var + 1e-5f);
            uint4 v = *(const uint4*)(sAc + row * SROW + q * 8);
            float2 v0 = __half22float2(*(half2*)&v.x);
            float2 v1 = __half22float2(*(half2*)&v.y);
            float2 v2 = __half22float2(*(half2*)&v.z);
            float2 v3 = __half22float2(*(half2*)&v.w);
            int c = q * 8;
            uint4 o;
            o.x = packh2(fmaxf((v0.x - mean) * rstd * s_g[c + 0] + s_bt[c + 0], 0.f),
                         fmaxf((v0.y - mean) * rstd * s_g[c + 1] + s_bt[c + 1], 0.f));
            o.y = packh2(fmaxf((v1.x - mean) * rstd * s_g[c + 2] + s_bt[c + 2], 0.f),
                         fmaxf((v1.y - mean) * rstd * s_g[c + 3] + s_bt[c + 3], 0.f));
            o.z = packh2(fmaxf((v2.x - mean) * rstd * s_g[c + 4] + s_bt[c + 4], 0.f),
                         fmaxf((v2.y - mean) * rstd * s_g[c + 5] + s_bt[c + 5], 0.f));
            o.w = packh2(fmaxf((v3.x - mean) * rstd * s_g[c + 6] + s_bt[c + 6], 0.f),
                         fmaxf((v3.y - mean) * rstd * s_g[c + 7] + s_bt[c + 7], 0.f));
            size_t off = (size_t)(n0 + row) * HD + c;
            *(uint4*)(out + off) = o;
            if (DUAL) *(uint4*)(hdup + off) = o;
        }
        pb ^= 1;
    }
}

// ---------------- pooling ----------------
__global__ void zero_pool() {
    int i = blockIdx.x * blockDim.x + threadIdx.x;
    if (i < NG * HD) g_pool[i] = 0.f;
    if (i < NG) g_cnt[i] = 0;
}

__global__ void pool128(const __half* __restrict__ x, const int* __restrict__ batch) {
    const int CHUNK = 50;
    int n0 = blockIdx.x * CHUNK;
    int n1 = n0 + CHUNK;
    if (n1 > NN) n1 = NN;
    int j = threadIdx.x;
    float acc = 0.f;
    int cnt = 0;
    int cur = batch[n0];
    for (int n = n0; n < n1; n++) {
        int g = batch[n];
        if (g != cur) {
            atomicAdd(&g_pool[cur * HD + j], acc);
            if (j == 0) atomicAdd(&g_cnt[cur], cnt);
            acc = 0.f; cnt = 0; cur = g;
        }
        acc += __half2float(x[(size_t)n * HD + j]);
        cnt++;
    }
    atomicAdd(&g_pool[cur * HD + j], acc);
    if (j == 0) atomicAdd(&g_cnt[cur], cnt);
}

__global__ void finalize(float* __restrict__ out) {
    int g = blockIdx.x, j = threadIdx.x;
    float s = g_pool[g * HD + j];
    int c = g_cnt[g];
    float cf = (float)(c > 1 ? c : 1);
    out[g * 2 * HD + j]      = s / cf;
    out[g * 2 * HD + HD + j] = s;
}

// ---------------------------------------------------------------------------
extern "C" void kernel_launch(void* const* d_in, const int* in_sizes, int n_in,
                              void* d_out, int out_size) {
    const float* x     = (const float*)d_in[0];
    const int*   ei    = (const int*)d_in[1];
    const float* ea    = (const float*)d_in[2];
    const int*   batch = (const int*)d_in[3];
    const float* P[24];
    for (int i = 0; i < 24; i++) P[i] = (const float*)d_in[4 + i];
    const int* esrc = ei;
    const int* edst = ei + NE;

    __half *h5h, *h, *bufA, *bufB;
    cudaGetSymbolAddress((void**)&h5h, g_h5h);
    cudaGetSymbolAddress((void**)&h, g_h);
    cudaGetSymbolAddress((void**)&bufA, g_bufA);
    cudaGetSymbolAddress((void**)&bufB, g_bufB);

    cudaFuncSetAttribute(mlp_tc<IND, true>, cudaFuncAttributeMaxDynamicSharedMemorySize, SMEM_TOT);
    cudaFuncSetAttribute(mlp_tc<HD, true>,  cudaFuncAttributeMaxDynamicSharedMemorySize, SMEM_TOT);
    cudaFuncSetAttribute(mlp_tc<HD, false>, cudaFuncAttributeMaxDynamicSharedMemorySize, SMEM_TOT);

    const int TB = 256;
    const int GEDGE = 3125;   // 3125*256/16 = 50000 edge slots, 8 iters

    // ---- layer 0 (din = 5, padded fp16) ----
    copy5h<<<(NN + TB - 1) / TB, TB>>>(x, h5h);
    edge5h<<<(NE + TB - 1) / TB, TB>>>(esrc, edst, ea, P[0], P[1], x);
    mlp_tc<IND, true><<<GRID_P, 256, SMEM_TOT>>>(h5h, P[2], P[3], P[4], P[5], P[6], P[7], bufA, h);

    // ---- layer 1 ----
    edge128h<<<GEDGE, TB>>>(esrc, edst, ea, P[8], P[9], bufA, h);
    mlp_tc<HD, true><<<GRID_P, 256, SMEM_TOT>>>(h, P[10], P[11], P[12], P[13], P[14], P[15], bufB, h);

    // ---- layer 2 ----
    edge128h<<<GEDGE, TB>>>(esrc, edst, ea, P[16], P[17], bufB, h);
    mlp_tc<HD, false><<<GRID_P, 256, SMEM_TOT>>>(h, P[18], P[19], P[20], P[21], P[22], P[23], bufA, nullptr);

    // ---- pooling ----
    zero_pool<<<(NG * HD + TB - 1) / TB, TB>>>();
    pool128<<<NN / 50, HD>>>(bufA, batch);
    finalize<<<NG, HD>>>((float*)d_out);
}

// round 13
// speedup vs baseline: 1.5632x; 1.0478x over previous
#include <cuda_runtime.h>
#include <cuda_fp16.h>

#define NN 200000
#define NE 400000
#define NG 64
#define HD 128
#define IND 5
#define L0W 16          // layer-0 padded row width (halves)
#define TROWS 64
#define SROW 136        // f16 tile row stride (halves): ldmatrix conflict-free
#define SPST 12         // partial-sum row stride (floats): 48B, 16B-aligned
#define GRID_P 304      // persistent CTAs (2 per SM, 152 SMs)

// ---------------- device scratch (allocation-free rule) ----------------
__device__ __half g_h5h[(size_t)NN * L0W];  // layer-0 padded fp16 (x + aggr)
__device__ __half g_h[(size_t)NN * HD];     // accumulation base (y + aggr), fp16
__device__ __half g_bufA[(size_t)NN * HD];  // layer outputs ping (fp16)
__device__ __half g_bufB[(size_t)NN * HD];  // layer outputs pong (fp16)
__device__ float  g_pool[NG * HD];
__device__ int    g_cnt[NG];

// ---------------- helpers ----------------
__device__ __forceinline__ unsigned packh2(float a, float b) {
    half2 h = __floats2half2_rn(a, b);
    return *(unsigned*)&h;
}
__device__ __forceinline__ void ldmA(unsigned a[4], unsigned saddr) {
    asm volatile("ldmatrix.sync.aligned.m8n8.x4.shared.b16 {%0,%1,%2,%3}, [%4];"
                 : "=r"(a[0]), "=r"(a[1]), "=r"(a[2]), "=r"(a[3]) : "r"(saddr));
}
__device__ __forceinline__ void mma16(float* d, const unsigned* a, unsigned b0, unsigned b1) {
    asm volatile("mma.sync.aligned.m16n8k16.row.col.f32.f16.f16.f32 "
                 "{%0,%1,%2,%3}, {%4,%5,%6,%7}, {%8,%9}, {%0,%1,%2,%3};"
                 : "+f"(d[0]), "+f"(d[1]), "+f"(d[2]), "+f"(d[3])
                 : "r"(a[0]), "r"(a[1]), "r"(a[2]), "r"(a[3]), "r"(b0), "r"(b1));
}
__device__ __forceinline__ void cp_async16(unsigned saddr, const void* gptr) {
    asm volatile("cp.async.cg.shared.global [%0], [%1], 16;" :: "r"(saddr), "l"(gptr));
}
#define CP_COMMIT() asm volatile("cp.async.commit_group;" ::: "memory")
#define CP_WAIT0()  asm volatile("cp.async.wait_group 0;" ::: "memory")

// ---------------- layer-0 prep ----------------
__global__ void copy5h(const float* __restrict__ x) {
    int n = blockIdx.x * blockDim.x + threadIdx.x;
    if (n >= NN) return;
    __half v[16];
#pragma unroll
    for (int j = 0; j < L0W; j++)
        v[j] = __float2half_rn(j < IND ? __ldg(x + n * IND + j) : 0.f);
    *(uint4*)(g_h5h + (size_t)n * L0W)     = *(uint4*)v;
    *(uint4*)(g_h5h + (size_t)n * L0W + 8) = *(uint4*)(v + 8);
}

__global__ void edge5h(const int* __restrict__ src, const int* __restrict__ dst,
                       const float* __restrict__ ea,
                       const float* __restrict__ ew, const float* __restrict__ eb,
                       const float* __restrict__ x) {
    int e = blockIdx.x * blockDim.x + threadIdx.x;
    if (e >= NE) return;
    int s = __ldg(src + e), d = __ldg(dst + e);
    float a = __ldg(ea + e);
    float m[IND];
#pragma unroll
    for (int j = 0; j < IND; j++)
        m[j] = fmaxf(__ldg(x + s * IND + j) + fmaf(a, __ldg(ew + j), __ldg(eb + j)), 0.f);
    unsigned p0 = packh2(m[0], m[1]);
    unsigned p1 = packh2(m[2], m[3]);
    __half h4 = __float2half_rn(m[4]);
    __half* pd = g_h5h + (size_t)d * L0W;
    asm volatile("red.global.add.noftz.v2.f16x2 [%0], {%1, %2};"
                 :: "l"(pd), "r"(p0), "r"(p1) : "memory");
    asm volatile("red.global.add.noftz.f16 [%0], %1;"
                 :: "l"(pd + 4), "h"(*(unsigned short*)&h4) : "memory");
}

// fp16 edge message + scatter (HD layers). Persistent; reg cap for occupancy.
__global__ void __launch_bounds__(256, 6) edge128h(
        const int* __restrict__ src, const int* __restrict__ dst,
        const float* __restrict__ ea,
        const float* __restrict__ ew, const float* __restrict__ eb,
        const __half* __restrict__ x, __half* __restrict__ h) {
    const int lane = threadIdx.x & 15;        // halves [lane*8, lane*8+8)
    const int g0 = (blockIdx.x * blockDim.x + threadIdx.x) >> 4;
    const int gs = (gridDim.x * blockDim.x) >> 4;
    const float4 w0 = __ldg((const float4*)ew + lane * 2);
    const float4 w1 = __ldg((const float4*)ew + lane * 2 + 1);
    const float4 c0 = __ldg((const float4*)eb + lane * 2);
    const float4 c1 = __ldg((const float4*)eb + lane * 2 + 1);
#pragma unroll 2
    for (int e = g0; e < NE; e += gs) {
        int s = __ldg(src + e), d = __ldg(dst + e);
        float a = __ldg(ea + e);
        uint4 xv = __ldg((const uint4*)(x + (size_t)s * HD) + lane);
        float2 x0 = __half22float2(*(half2*)&xv.x);
        float2 x1 = __half22float2(*(half2*)&xv.y);
        float2 x2 = __half22float2(*(half2*)&xv.z);
        float2 x3 = __half22float2(*(half2*)&xv.w);
        unsigned m0 = packh2(fmaxf(x0.x + fmaf(a, w0.x, c0.x), 0.f),
                             fmaxf(x0.y + fmaf(a, w0.y, c0.y), 0.f));
        unsigned m1 = packh2(fmaxf(x1.x + fmaf(a, w0.z, c0.z), 0.f),
                             fmaxf(x1.y + fmaf(a, w0.w, c0.w), 0.f));
        unsigned m2 = packh2(fmaxf(x2.x + fmaf(a, w1.x, c1.x), 0.f),
                             fmaxf(x2.y + fmaf(a, w1.y, c1.y), 0.f));
        unsigned m3 = packh2(fmaxf(x3.x + fmaf(a, w1.z, c1.z), 0.f),
                             fmaxf(x3.y + fmaf(a, w1.w, c1.w), 0.f));
        __half* p = h + (size_t)d * HD + lane * 8;
        asm volatile("red.global.add.noftz.v4.f16x2 [%0], {%1, %2, %3, %4};"
                     :: "l"(p), "r"(m0), "r"(m1), "r"(m2), "r"(m3) : "memory");
    }
}

// ---------------- fused MLP + LN (+ fused pooling), fp16 m16n8k16 ----------------
// smem (bytes): [0,3072) params | sA0 | sA1 | sMid | sp | batch ids
#define TILEB   (TROWS * SROW * 2)         // 17408
#define OFF_A0  3072
#define OFF_A1  (OFF_A0 + TILEB)
#define OFF_MID (OFF_A1 + TILEB)
#define OFF_SP  (OFF_MID + TILEB)
#define OFF_BT  (OFF_SP + 2 * TROWS * SPST * 4)
#define SMEM_TOT (OFF_BT + TROWS * 4)
#define NTILE (NN / TROWS)

template <int DIN, bool DUAL>
__global__ void __launch_bounds__(256, 2) mlp_tc(
        const __half* __restrict__ hin,
        const float* __restrict__ w1, const float* __restrict__ b1,
        const float* __restrict__ w2, const float* __restrict__ b2,
        const float* __restrict__ gam, const float* __restrict__ bet,
        __half* __restrict__ out, __half* __restrict__ hdup,
        const int* __restrict__ batch) {
    extern __shared__ char smem[];
    float* s_b1 = (float*)smem;
    float* s_b2 = s_b1 + 128;
    float* s_g  = s_b1 + 256;
    float* s_bt = s_b1 + 384;
    half*  sA0  = (half*)(smem + OFF_A0);
    half*  sA1  = (half*)(smem + OFF_A1);
    half*  sMid = (half*)(smem + OFF_MID);
    float* sp_s = (float*)(smem + OFF_SP);
    float* sp_q = sp_s + TROWS * SPST;
    int*   sbat = (int*)(smem + OFF_BT);

    const int tid = threadIdx.x;
    const int w = tid >> 5, lane = tid & 31;
    const int qr = lane >> 2, qc = lane & 3;
    const int wbase = w * 16;
    const int lm_r = ((lane >> 3) & 1) * 8 + (lane & 7);
    const int lm_c = (lane >> 4) * 8;
    constexpr int NCP = (DIN == HD) ? 16 : 2;   // A-row width in 8-half groups
    constexpr bool POOL = !DUAL;                // layer-2 instantiation pools

    if (tid < 128) {
        s_b1[tid] = __ldg(b1 + tid);
        s_b2[tid] = __ldg(b2 + tid);
        s_g[tid]  = __ldg(gam + tid);
        s_bt[tid] = __ldg(bet + tid);
    }

    // ---- W fragments: loaded ONCE per persistent CTA ----
    constexpr int NKS1 = (DIN == HD) ? 8 : 1;
    unsigned wf1[2][NKS1][2], wf2[2][8][2];
#pragma unroll
    for (int nt = 0; nt < 2; nt++) {
        int n = wbase + nt * 8 + qr;
#pragma unroll
        for (int kk = 0; kk < NKS1; kk++) {
            int k0 = kk * 16 + 2 * qc;
            float f0 = (k0 < DIN)     ? __ldg(w1 + (size_t)k0 * HD + n)       : 0.f;
            float f1 = (k0 + 1 < DIN) ? __ldg(w1 + (size_t)(k0 + 1) * HD + n) : 0.f;
            float f2 = (k0 + 8 < DIN) ? __ldg(w1 + (size_t)(k0 + 8) * HD + n) : 0.f;
            float f3 = (k0 + 9 < DIN) ? __ldg(w1 + (size_t)(k0 + 9) * HD + n) : 0.f;
            wf1[nt][kk][0] = packh2(f0, f1);
            wf1[nt][kk][1] = packh2(f2, f3);
        }
#pragma unroll
        for (int kk = 0; kk < 8; kk++) {
            int k0 = kk * 16 + 2 * qc;
            wf2[nt][kk][0] = packh2(__ldg(w2 + (size_t)k0 * HD + n),
                                    __ldg(w2 + (size_t)(k0 + 1) * HD + n));
            wf2[nt][kk][1] = packh2(__ldg(w2 + (size_t)(k0 + 8) * HD + n),
                                    __ldg(w2 + (size_t)(k0 + 9) * HD + n));
        }
    }
    __syncthreads();

    const unsigned sMid_base = (unsigned)__cvta_generic_to_shared(sMid);
    const unsigned sA0_base  = (unsigned)__cvta_generic_to_shared(sA0);
    const unsigned sA1_base  = (unsigned)__cvta_generic_to_shared(sA1);

    // prime: prefetch first tile into sA0
    int pb = 0;
    {
        int n0 = blockIdx.x * TROWS;
        for (int idx = tid; idx < TROWS * NCP; idx += 256) {
            int row = idx / NCP, q = idx % NCP;
            cp_async16(sA0_base + (row * SROW + q * 8) * 2,
                       hin + (size_t)(n0 + row) * (NCP * 8) + q * 8);
        }
        CP_COMMIT();
    }

    for (int tile = blockIdx.x; tile < NTILE; tile += GRID_P) {
        const int n0 = tile * TROWS;
        half* sAc = pb ? sA1 : sA0;
        const unsigned sAc_base = pb ? sA1_base : sA0_base;

        CP_WAIT0();
        __syncthreads();                 // A_t visible; prev-tile smem reuse done
        int tn = tile + GRID_P;
        if (tn < NTILE) {                // prefetch next tile into alternate buf
            const unsigned sAn_base = pb ? sA0_base : sA1_base;
            int m0 = tn * TROWS;
            for (int idx = tid; idx < TROWS * NCP; idx += 256) {
                int row = idx / NCP, q = idx % NCP;
                cp_async16(sAn_base + (row * SROW + q * 8) * 2,
                           hin + (size_t)(m0 + row) * (NCP * 8) + q * 8);
            }
        }
        CP_COMMIT();
        if (POOL && tid < TROWS) sbat[tid] = __ldg(batch + n0 + tid);

        // ---- GEMM1 + bias1 + ReLU -> sMid ----
#pragma unroll 1
        for (int mt = 0; mt < TROWS / 16; mt++) {
            float d0[4] = {0, 0, 0, 0}, d1[4] = {0, 0, 0, 0};
            int r0 = mt * 16;
#pragma unroll
            for (int kk = 0; kk < NKS1; kk++) {
                unsigned a[4];
                ldmA(a, sAc_base + ((r0 + lm_r) * SROW + kk * 16 + lm_c) * 2);
                mma16(d0, a, wf1[0][kk][0], wf1[0][kk][1]);
                mma16(d1, a, wf1[1][kk][0], wf1[1][kk][1]);
            }
#pragma unroll
            for (int nt = 0; nt < 2; nt++) {
                float* d = nt ? d1 : d0;
                int c0 = wbase + nt * 8 + 2 * qc;
                *(unsigned*)(sMid + (r0 + qr) * SROW + c0) =
                    packh2(fmaxf(d[0] + s_b1[c0], 0.f), fmaxf(d[1] + s_b1[c0 + 1], 0.f));
                *(unsigned*)(sMid + (r0 + 8 + qr) * SROW + c0) =
                    packh2(fmaxf(d[2] + s_b1[c0], 0.f), fmaxf(d[3] + s_b1[c0 + 1], 0.f));
            }
        }
        __syncthreads();

        // ---- GEMM2 + bias2: partial LN sums -> sp, fp16 values -> sAc ----
#pragma unroll 1
        for (int mt = 0; mt < TROWS / 16; mt++) {
            float d0[4] = {0, 0, 0, 0}, d1[4] = {0, 0, 0, 0};
            int r0 = mt * 16;
#pragma unroll
            for (int kk = 0; kk < 8; kk++) {
                unsigned a[4];
                ldmA(a, sMid_base + ((r0 + lm_r) * SROW + kk * 16 + lm_c) * 2);
                mma16(d0, a, wf2[0][kk][0], wf2[0][kk][1]);
                mma16(d1, a, wf2[1][kk][0], wf2[1][kk][1]);
            }
            {
                int c0 = wbase + 2 * qc, c1 = wbase + 8 + 2 * qc;
                d0[0] += s_b2[c0]; d0[1] += s_b2[c0 + 1];
                d0[2] += s_b2[c0]; d0[3] += s_b2[c0 + 1];
                d1[0] += s_b2[c1]; d1[1] += s_b2[c1 + 1];
                d1[2] += s_b2[c1]; d1[3] += s_b2[c1 + 1];
            }
            float sa = d0[0] + d0[1] + d1[0] + d1[1];
            float sb = d0[2] + d0[3] + d1[2] + d1[3];
            float qa = d0[0] * d0[0] + d0[1] * d0[1] + d1[0] * d1[0] + d1[1] * d1[1];
            float qb = d0[2] * d0[2] + d0[3] * d0[3] + d1[2] * d1[2] + d1[3] * d1[3];
#pragma unroll
            for (int o = 1; o <= 2; o <<= 1) {
                sa += __shfl_xor_sync(0xffffffffu, sa, o);
                sb += __shfl_xor_sync(0xffffffffu, sb, o);
                qa += __shfl_xor_sync(0xffffffffu, qa, o);
                qb += __shfl_xor_sync(0xffffffffu, qb, o);
            }
            if (qc == 0) {
                sp_s[(r0 + qr) * SPST + w] = sa;
                sp_s[(r0 + 8 + qr) * SPST + w] = sb;
                sp_q[(r0 + qr) * SPST + w] = qa;
                sp_q[(r0 + 8 + qr) * SPST + w] = qb;
            }
            {
                int c0 = wbase + 2 * qc;
                *(unsigned*)(sAc + (r0 + qr) * SROW + c0)      = packh2(d0[0], d0[1]);
                *(unsigned*)(sAc + (r0 + qr) * SROW + c0 + 8)  = packh2(d1[0], d1[1]);
                *(unsigned*)(sAc + (r0 + 8 + qr) * SROW + c0)     = packh2(d0[2], d0[3]);
                *(unsigned*)(sAc + (r0 + 8 + qr) * SROW + c0 + 8) = packh2(d1[2], d1[3]);
            }
        }
        __syncthreads();

        // ---- LN apply + ReLU + coalesced fp16 store (dual / pool stash) ----
        for (int idx = tid; idx < TROWS * 16; idx += 256) {
            int row = idx >> 4, q = idx & 15;
            float4 sa = *(const float4*)(sp_s + row * SPST);
            float4 sb = *(const float4*)(sp_s + row * SPST + 4);
            float4 qa = *(const float4*)(sp_q + row * SPST);
            float4 qb = *(const float4*)(sp_q + row * SPST + 4);
            float s  = sa.x + sa.y + sa.z + sa.w + sb.x + sb.y + sb.z + sb.w;
            float s2 = qa.x + qa.y + qa.z + qa.w + qb.x + qb.y + qb.z + qb.w;
            float mean = s * (1.f / HD);
            float var = s2 * (1.f / HD) - mean * mean;
            float rstd = rsqrtf(var + 1e-5f);
            uint4 v = *(const uint4*)(sAc + row * SROW + q * 8);
            float2 v0 = __half22float2(*(half2*)&v.x);
            float2 v1 = __half22float2(*(half2*)&v.y);
            float2 v2 = __half22float2(*(half2*)&v.z);
            float2 v3 = __half22float2(*(half2*)&v.w);
            int c = q * 8;
            uint4 o;
            o.x = packh2(fmaxf((v0.x - mean) * rstd * s_g[c + 0] + s_bt[c + 0], 0.f),
                         fmaxf((v0.y - mean) * rstd * s_g[c + 1] + s_bt[c + 1], 0.f));
            o.y = packh2(fmaxf((v1.x - mean) * rstd * s_g[c + 2] + s_bt[c + 2], 0.f),
                         fmaxf((v1.y - mean) * rstd * s_g[c + 3] + s_bt[c + 3], 0.f));
            o.z = packh2(fmaxf((v2.x - mean) * rstd * s_g[c + 4] + s_bt[c + 4], 0.f),
                         fmaxf((v2.y - mean) * rstd * s_g[c + 5] + s_bt[c + 5], 0.f));
            o.w = packh2(fmaxf((v3.x - mean) * rstd * s_g[c + 6] + s_bt[c + 6], 0.f),
                         fmaxf((v3.y - mean) * rstd * s_g[c + 7] + s_bt[c + 7], 0.f));
            size_t off = (size_t)(n0 + row) * HD + c;
            *(uint4*)(out + off) = o;
            if (DUAL) *(uint4*)(hdup + off) = o;
            if (POOL) *(uint4*)(sMid + row * SROW + c) = o;   // stash for pooling
        }

        // ---- fused pooling: segmented per-graph reduction over tile rows ----
        if (POOL) {
            __syncthreads();             // sMid stashes + sbat visible
            if (tid < HD) {
                int j = tid;
                float acc = 0.f;
                int cnt = 0, cur = sbat[0];
                for (int r = 0; r < TROWS; r++) {
                    int gp = sbat[r];
                    if (gp != cur) {
                        atomicAdd(&g_pool[cur * HD + j], acc);
                        if (j == 0) atomicAdd(&g_cnt[cur], cnt);
                        acc = 0.f; cnt = 0; cur = gp;
                    }
                    acc += __half2float(sMid[r * SROW + j]);
                    cnt++;
                }
                atomicAdd(&g_pool[cur * HD + j], acc);
                if (j == 0) atomicAdd(&g_cnt[cur], cnt);
            }
        }
        pb ^= 1;
    }
}

// ---------------- pooling epilogue ----------------
__global__ void zero_pool() {
    int i = blockIdx.x * blockDim.x + threadIdx.x;
    if (i < NG * HD) g_pool[i] = 0.f;
    if (i < NG) g_cnt[i] = 0;
}

__global__ void finalize(float* __restrict__ out) {
    int g = blockIdx.x, j = threadIdx.x;
    float s = g_pool[g * HD + j];
    int c = g_cnt[g];
    float cf = (float)(c > 1 ? c : 1);
    out[g * 2 * HD + j]      = s / cf;
    out[g * 2 * HD + HD + j] = s;
}

// ---------------------------------------------------------------------------
extern "C" void kernel_launch(void* const* d_in, const int* in_sizes, int n_in,
                              void* d_out, int out_size) {
    const float* x     = (const float*)d_in[0];
    const int*   ei    = (const int*)d_in[1];
    const float* ea    = (const float*)d_in[2];
    const int*   batch = (const int*)d_in[3];
    const float* P[24];
    for (int i = 0; i < 24; i++) P[i] = (const float*)d_in[4 + i];
    const int* esrc = ei;
    const int* edst = ei + NE;

    __half *h5h, *h, *bufA, *bufB;
    cudaGetSymbolAddress((void**)&h5h, g_h5h);
    cudaGetSymbolAddress((void**)&h, g_h);
    cudaGetSymbolAddress((void**)&bufA, g_bufA);
    cudaGetSymbolAddress((void**)&bufB, g_bufB);

    cudaFuncSetAttribute(mlp_tc<IND, true>, cudaFuncAttributeMaxDynamicSharedMemorySize, SMEM_TOT);
    cudaFuncSetAttribute(mlp_tc<HD, true>,  cudaFuncAttributeMaxDynamicSharedMemorySize, SMEM_TOT);
    cudaFuncSetAttribute(mlp_tc<HD, false>, cudaFuncAttributeMaxDynamicSharedMemorySize, SMEM_TOT);

    const int TB = 256;
    const int GEDGE = 3125;   // 3125*256/16 = 50000 edge slots, 8 iters

    // ---- layer 0 (din = 5, padded fp16) ----
    copy5h<<<(NN + TB - 1) / TB, TB>>>(x);
    edge5h<<<(NE + TB - 1) / TB, TB>>>(esrc, edst, ea, P[0], P[1], x);
    mlp_tc<IND, true><<<GRID_P, 256, SMEM_TOT>>>(h5h, P[2], P[3], P[4], P[5], P[6], P[7], bufA, h, nullptr);

    // ---- layer 1 ----
    edge128h<<<GEDGE, TB>>>(esrc, edst, ea, P[8], P[9], bufA, h);
    mlp_tc<HD, true><<<GRID_P, 256, SMEM_TOT>>>(h, P[10], P[11], P[12], P[13], P[14], P[15], bufB, h, nullptr);

    // ---- layer 2 (pooling fused into epilogue) ----
    zero_pool<<<(NG * HD + TB - 1) / TB, TB>>>();
    edge128h<<<GEDGE, TB>>>(esrc, edst, ea, P[16], P[17], bufB, h);
    mlp_tc<HD, false><<<GRID_P, 256, SMEM_TOT>>>(h, P[18], P[19], P[20], P[21], P[22], P[23], bufA, nullptr, batch);

    // ---- finalize ----
    finalize<<<NG, HD>>>((float*)d_out);
}